// round 11
// baseline (speedup 1.0000x reference)
#include <cuda_runtime.h>
#include <cuda_bf16.h>
#include <cstddef>

// Problem constants (fixed shapes from the reference)
constexpr int NN = 50000;     // nodes
constexpr int EE = 1600000;   // edges (before self loops)
constexpr int HH = 4;         // heads
constexpr int CC = 32;        // channels per head
constexpr int HC = HH * CC;   // 128
constexpr int INC = 256;      // in_channels
constexpr int OUTC = 64;      // out_channels
constexpr float NEG_SLOPE = 0.2f;

// ---------------- scratch (device globals; no allocation allowed) ----------
__device__ float g_h[(size_t)NN * HC];     // 25.6 MB  x@W
__device__ float g_agg[(size_t)NN * HC];   // 25.6 MB  attention-aggregated
__device__ float g_asrc[NN * HH];
__device__ float g_adst[NN * HH];
__device__ int   g_deg[NN];
__device__ int   g_off[NN + 1];
__device__ int   g_cur[NN];
__device__ int   g_csr[EE];                // 6.4 MB  src ids grouped by dst
__device__ int   g_is64;                   // edge_index dtype flag (device-decided)

__device__ __forceinline__ float eluf(float x) {
    return x > 0.f ? x : (__expf(x) - 1.f);
}

__device__ __forceinline__ int clampN(int v) {
    v = v < 0 ? 0 : v;
    return v >= NN ? NN - 1 : v;
}

// Read edge endpoint `pos` (0..2*EE-1) honoring detected dtype.
__device__ __forceinline__ int edge_at(const void* ei, int pos) {
    if (g_is64) return clampN((int)((const long long*)ei)[pos]);
    return clampN(((const int*)ei)[pos]);
}

// ---------------- dtype detection ------------------------------------------
// int64 indices < 2^31 have zero high words at odd int32 positions. Genuine
// random int32 indices in [0,50000) are nonzero at odd positions w.p.
// ~(1 - 2e-5) each -> 128 consecutive zeros is impossible in practice.
__global__ void detect_kernel(const int* __restrict__ ei32) {
    int all0 = 1;
    for (int k = 0; k < 128; k++)
        if (ei32[2 * k + 1] != 0) { all0 = 0; break; }
    g_is64 = all0;
}

// ---------------- generic register-blocked SGEMM ---------------------------
// C[M,N] = transform(A)[M,K] @ B[K,N]  (+ optional output bias)
// ELUIN:    A element -> elu(a + abias[k])   (fuses GAT epilogue into GEMM2)
// AIN_GAGG: read A from device-global g_agg (ignore A_ param)
// COUT_GH:  write C to device-global g_h   (ignore C_ param)
template<int BM, int BN, int BK, int TM, int TN,
         bool ELUIN, bool OBIAS, bool AIN_GAGG, bool COUT_GH>
__global__ void __launch_bounds__((BM / TM) * (BN / TN))
gemm_kernel(const float* __restrict__ A_, const float* __restrict__ B,
            const float* __restrict__ abias, const float* __restrict__ obias,
            float* __restrict__ C_, int M, int Nn, int K)
{
    const float* __restrict__ A = AIN_GAGG ? (const float*)g_agg : A_;
    float* __restrict__ C = COUT_GH ? (float*)g_h : C_;

    constexpr int NT = (BM / TM) * (BN / TN);
    __shared__ float As[BK][BM];   // stored transposed: [k][m]
    __shared__ float Bs[BK][BN];

    const int tid = threadIdx.x;
    const int m0 = blockIdx.x * BM;
    const int n0 = blockIdx.y * BN;
    const int tx = tid % (BN / TN);
    const int ty = tid / (BN / TN);

    float acc[TM][TN];
#pragma unroll
    for (int i = 0; i < TM; i++)
#pragma unroll
        for (int j = 0; j < TN; j++) acc[i][j] = 0.f;

    for (int k0 = 0; k0 < K; k0 += BK) {
        // load A tile (float4 along K, coalesced), transpose into As
#pragma unroll
        for (int base = 0; base < BM * BK / 4; base += NT) {
            int idx = base + tid;
            int ar = idx / (BK / 4);
            int ac = (idx % (BK / 4)) * 4;
            float4 v = make_float4(0.f, 0.f, 0.f, 0.f);
            int row = m0 + ar;
            if (row < M) v = *(const float4*)&A[(size_t)row * K + k0 + ac];
            if (ELUIN) {
                v.x = eluf(v.x + abias[k0 + ac + 0]);
                v.y = eluf(v.y + abias[k0 + ac + 1]);
                v.z = eluf(v.z + abias[k0 + ac + 2]);
                v.w = eluf(v.w + abias[k0 + ac + 3]);
            }
            As[ac + 0][ar] = v.x;
            As[ac + 1][ar] = v.y;
            As[ac + 2][ar] = v.z;
            As[ac + 3][ar] = v.w;
        }
        // load B tile (K,N divisible by BK,BN in all our uses)
#pragma unroll
        for (int base = 0; base < BK * BN / 4; base += NT) {
            int idx = base + tid;
            int br = idx / (BN / 4);
            int bc = (idx % (BN / 4)) * 4;
            *(float4*)&Bs[br][bc] = *(const float4*)&B[(size_t)(k0 + br) * Nn + n0 + bc];
        }
        __syncthreads();

#pragma unroll
        for (int kk = 0; kk < BK; kk++) {
            float a[TM], b[TN];
#pragma unroll
            for (int i = 0; i < TM; i++) a[i] = As[kk][ty * TM + i];
#pragma unroll
            for (int j = 0; j < TN; j++) b[j] = Bs[kk][tx * TN + j];
#pragma unroll
            for (int i = 0; i < TM; i++)
#pragma unroll
                for (int j = 0; j < TN; j++) acc[i][j] += a[i] * b[j];
        }
        __syncthreads();
    }

#pragma unroll
    for (int i = 0; i < TM; i++) {
        int row = m0 + ty * TM + i;
        if (row < M) {
#pragma unroll
            for (int j = 0; j < TN; j += 4) {
                int col = n0 + tx * TN + j;
                float4 v;
                v.x = acc[i][j + 0]; v.y = acc[i][j + 1];
                v.z = acc[i][j + 2]; v.w = acc[i][j + 3];
                if (OBIAS) {
                    v.x += obias[col + 0]; v.y += obias[col + 1];
                    v.z += obias[col + 2]; v.w += obias[col + 3];
                }
                *(float4*)&C[(size_t)row * Nn + col] = v;
            }
        }
    }
}

// ---------------- per-node attention halves --------------------------------
// a_src[n,h] = sum_c h[n,h,c]*att_src[h,c]; one warp per node; lane l owns
// channels 4l..4l+3 (head l>>3); 8-lane tree reduction.
__global__ void __launch_bounds__(256) att_kernel(const float* __restrict__ att_s,
                                                  const float* __restrict__ att_d)
{
    int gw = (blockIdx.x * blockDim.x + threadIdx.x) >> 5;
    int lane = threadIdx.x & 31;
    if (gw >= NN) return;
    float4 hv = ((const float4*)g_h)[(size_t)gw * 32 + lane];
    float4 s4 = ((const float4*)att_s)[lane];
    float4 d4 = ((const float4*)att_d)[lane];
    float ps = hv.x * s4.x + hv.y * s4.y + hv.z * s4.z + hv.w * s4.w;
    float pd = hv.x * d4.x + hv.y * d4.y + hv.z * d4.z + hv.w * d4.w;
#pragma unroll
    for (int off = 1; off < 8; off <<= 1) {
        ps += __shfl_xor_sync(0xffffffffu, ps, off);
        pd += __shfl_xor_sync(0xffffffffu, pd, off);
    }
    if ((lane & 7) == 0) {
        g_asrc[gw * 4 + (lane >> 3)] = ps;
        g_adst[gw * 4 + (lane >> 3)] = pd;
    }
}

// ---------------- CSR-by-dst build ------------------------------------------
__global__ void init_deg_kernel() {
    int i = blockIdx.x * blockDim.x + threadIdx.x;
    if (i < NN) g_deg[i] = 0;
}

__global__ void deg_kernel(const void* __restrict__ ei) {
    int e = blockIdx.x * blockDim.x + threadIdx.x;
    if (e < EE) {
        int d = edge_at(ei, EE + e);
        atomicAdd(&g_deg[d], 1);
    }
}

// single-block exclusive scan over g_deg -> g_off / g_cur; g_off[NN] = total
__global__ void __launch_bounds__(1024) scan_kernel() {
    __shared__ int sm[1024];
    __shared__ int s_run;
    int t = threadIdx.x;
    if (t == 0) s_run = 0;
    __syncthreads();
    for (int base = 0; base < NN; base += 1024) {
        int v = (base + t < NN) ? g_deg[base + t] : 0;
        sm[t] = v;
        __syncthreads();
#pragma unroll
        for (int off = 1; off < 1024; off <<= 1) {
            int u = (t >= off) ? sm[t - off] : 0;
            __syncthreads();
            sm[t] += u;
            __syncthreads();
        }
        int incl = sm[t];
        int run = s_run;
        if (base + t < NN) {
            int o = run + incl - v;
            g_off[base + t] = o;
            g_cur[base + t] = o;
        }
        __syncthreads();
        if (t == 1023) s_run = run + sm[1023];
        __syncthreads();
    }
    if (t == 0) g_off[NN] = s_run;
}

__global__ void scatter_kernel(const void* __restrict__ ei) {
    int e = blockIdx.x * blockDim.x + threadIdx.x;
    if (e < EE) {
        int s = edge_at(ei, e);
        int d = edge_at(ei, EE + e);
        int p = atomicAdd(&g_cur[d], 1);
        g_csr[p] = s;
    }
}

// ---------------- GAT softmax + aggregation ---------------------------------
// One warp per destination node. Lane l: channels 4l..4l+3, head hl = l>>3.
// exp(max) subtraction cancels exactly in alpha = ex/denom, so it is skipped;
// logits are O(1) so __expf never overflows. Self loop folded in directly.
// Lanes of the same head compute identical ex/denom -> no reduction needed.
__global__ void __launch_bounds__(256) gat_agg_kernel() {
    int i = (blockIdx.x * blockDim.x + threadIdx.x) >> 5;
    int lane = threadIdx.x & 31;
    if (i >= NN) return;
    int hl = lane >> 3;

    const float4* __restrict__ h4 = (const float4*)g_h;

    float ad = g_adst[i * 4 + hl];

    // self loop
    float as = g_asrc[i * 4 + hl];
    float e = as + ad;
    e = e > 0.f ? e : NEG_SLOPE * e;
    float ex = __expf(e);
    float denom = ex;
    float4 hv = h4[(size_t)i * 32 + lane];
    float4 acc;
    acc.x = ex * hv.x; acc.y = ex * hv.y; acc.z = ex * hv.z; acc.w = ex * hv.w;

    int s = g_off[i], t = g_off[i + 1];
    if (s < t) {
        int j = g_csr[s];                    // 1-deep prefetch of next src id
        for (int k = s; k < t; k++) {
            int jn = (k + 1 < t) ? g_csr[k + 1] : 0;
            float asj = __ldg(&g_asrc[j * 4 + hl]);
            float4 hj = h4[(size_t)j * 32 + lane];
            float ej = asj + ad;
            ej = ej > 0.f ? ej : NEG_SLOPE * ej;
            float exj = __expf(ej);
            denom += exj;
            acc.x += exj * hj.x; acc.y += exj * hj.y;
            acc.z += exj * hj.z; acc.w += exj * hj.w;
            j = jn;
        }
    }
    float inv = 1.f / denom;
    float4 o;
    o.x = acc.x * inv; o.y = acc.y * inv; o.z = acc.z * inv; o.w = acc.w * inv;
    ((float4*)g_agg)[(size_t)i * 32 + lane] = o;
}

// ---------------- launch ----------------------------------------------------
extern "C" void kernel_launch(void* const* d_in, const int* in_sizes, int n_in,
                              void* d_out, int out_size)
{
    const float* x      = (const float*)d_in[0];
    const void*  ei     = d_in[1];           // int32 or int64 — detected on device
    const float* W      = (const float*)d_in[2];
    const float* att_s  = (const float*)d_in[3];
    const float* att_d  = (const float*)d_in[4];
    const float* bias   = (const float*)d_in[5];
    const float* linW   = (const float*)d_in[6];
    const float* linb   = (const float*)d_in[7];
    float* out = (float*)d_out;

    detect_kernel<<<1, 1>>>((const int*)ei);
    init_deg_kernel<<<(NN + 255) / 256, 256>>>();

    // h = x @ W   [50000,256]x[256,128]  (C -> g_h via template flag)
    gemm_kernel<64, 128, 16, 8, 4, false, false, false, true>
        <<<dim3((NN + 63) / 64, 1), 256>>>(x, W, nullptr, nullptr, nullptr, NN, HC, INC);

    att_kernel<<<(NN + 7) / 8, 256>>>(att_s, att_d);

    deg_kernel<<<(EE + 255) / 256, 256>>>(ei);
    scan_kernel<<<1, 1024>>>();
    scatter_kernel<<<(EE + 255) / 256, 256>>>(ei);

    gat_agg_kernel<<<(NN + 7) / 8, 256>>>();

    // out = elu(agg + bias) @ lin_W + lin_b   [50000,128]x[128,64]  (A <- g_agg)
    gemm_kernel<128, 64, 16, 8, 4, true, true, true, false>
        <<<dim3((NN + 127) / 128, 1), 256>>>(nullptr, linW, bias, linb, out, NN, OUTC, HC);
}

// round 13
// speedup vs baseline: 1.1574x; 1.1574x over previous
#include <cuda_runtime.h>
#include <cuda_bf16.h>
#include <cstddef>

// Problem constants (fixed shapes from the reference)
constexpr int NN = 50000;     // nodes
constexpr int EE = 1600000;   // edges (before self loops)
constexpr int HH = 4;         // heads
constexpr int CC = 32;        // channels per head
constexpr int HC = HH * CC;   // 128
constexpr int INC = 256;      // in_channels
constexpr int OUTC = 64;      // out_channels
constexpr float NEG_SLOPE = 0.2f;

// ---------------- scratch (device globals; no allocation allowed) ----------
__device__ float g_h[(size_t)NN * HC];     // 25.6 MB  x@W
__device__ float g_agg[(size_t)NN * HC];   // 25.6 MB  attention-aggregated
__device__ float g_asrc[NN * HH];
__device__ float g_adst[NN * HH];
__device__ int   g_deg[NN];
__device__ int   g_off[NN + 1];
__device__ int   g_cur[NN];
__device__ int   g_csr[EE];                // 6.4 MB  src ids grouped by dst
__device__ int   g_is64;                   // edge_index dtype flag (device-decided)

__device__ __forceinline__ float eluf(float x) {
    return x > 0.f ? x : (__expf(x) - 1.f);
}

__device__ __forceinline__ int clampN(int v) {
    v = v < 0 ? 0 : v;
    return v >= NN ? NN - 1 : v;
}

// Read edge endpoint `pos` (0..2*EE-1) honoring detected dtype.
__device__ __forceinline__ int edge_at(const void* ei, int pos) {
    if (g_is64) return clampN((int)((const long long*)ei)[pos]);
    return clampN(((const int*)ei)[pos]);
}

// packed f32x2 helpers (Blackwell native; ptxas never auto-fuses these)
__device__ __forceinline__ unsigned long long pack2(float lo, float hi) {
    unsigned long long r;
    asm("mov.b64 %0, {%1, %2};" : "=l"(r) : "f"(lo), "f"(hi));
    return r;
}
__device__ __forceinline__ float2 unpack2(unsigned long long p) {
    float2 v;
    asm("mov.b64 {%0, %1}, %2;" : "=f"(v.x), "=f"(v.y) : "l"(p));
    return v;
}

// ---------------- dtype detection ------------------------------------------
// int64 indices < 2^31 have zero high words at odd int32 positions. Genuine
// random int32 indices in [0,50000) are nonzero at odd positions w.p.
// ~(1 - 2e-5) each -> 128 consecutive zeros is impossible in practice.
__global__ void detect_kernel(const int* __restrict__ ei32) {
    int all0 = 1;
    for (int k = 0; k < 128; k++)
        if (ei32[2 * k + 1] != 0) { all0 = 0; break; }
    g_is64 = all0;
}

// ---------------- register-blocked SGEMM with packed f32x2 FMA -------------
// C[M,N] = transform(A)[M,K] @ B[K,N]  (+ optional output bias)
// ELUIN:    A element -> elu(a + abias[k])   (fuses GAT epilogue into GEMM2)
// AIN_GAGG: read A from device-global g_agg (ignore A_ param)
// COUT_GH:  write C to device-global g_h   (ignore C_ param)
// ATTOUT:   also emit g_asrc/g_adst from the C tile (GEMM1 epilogue fusion;
//           requires BN==128 and BN/TN==32 so lane==tx)
template<int BM, int BN, int BK, int TM, int TN,
         bool ELUIN, bool OBIAS, bool AIN_GAGG, bool COUT_GH, bool ATTOUT>
__global__ void __launch_bounds__((BM / TM) * (BN / TN))
gemm_kernel(const float* __restrict__ A_, const float* __restrict__ B,
            const float* __restrict__ abias, const float* __restrict__ obias,
            const float* __restrict__ att_s, const float* __restrict__ att_d,
            float* __restrict__ C_, int M, int Nn, int K)
{
    static_assert(TN == 4 && TM % 4 == 0, "packed path assumes TN=4, TM%4==0");
    const float* __restrict__ A = AIN_GAGG ? (const float*)g_agg : A_;
    float* __restrict__ C = COUT_GH ? (float*)g_h : C_;

    constexpr int NT = (BM / TM) * (BN / TN);
    __shared__ float As[BK][BM];   // stored transposed: [k][m]
    __shared__ float Bs[BK][BN];

    const int tid = threadIdx.x;
    const int m0 = blockIdx.x * BM;
    const int n0 = blockIdx.y * BN;
    const int tx = tid % (BN / TN);
    const int ty = tid / (BN / TN);

    unsigned long long acc[TM][2];      // packed f32x2 pairs (cols 0-1, 2-3)
#pragma unroll
    for (int i = 0; i < TM; i++) { acc[i][0] = 0ull; acc[i][1] = 0ull; }

    for (int k0 = 0; k0 < K; k0 += BK) {
        // load A tile (float4 along K, coalesced), transpose into As
#pragma unroll
        for (int base = 0; base < BM * BK / 4; base += NT) {
            int idx = base + tid;
            int ar = idx / (BK / 4);
            int ac = (idx % (BK / 4)) * 4;
            float4 v = make_float4(0.f, 0.f, 0.f, 0.f);
            int row = m0 + ar;
            if (row < M) v = *(const float4*)&A[(size_t)row * K + k0 + ac];
            if (ELUIN) {
                v.x = eluf(v.x + abias[k0 + ac + 0]);
                v.y = eluf(v.y + abias[k0 + ac + 1]);
                v.z = eluf(v.z + abias[k0 + ac + 2]);
                v.w = eluf(v.w + abias[k0 + ac + 3]);
            }
            As[ac + 0][ar] = v.x;
            As[ac + 1][ar] = v.y;
            As[ac + 2][ar] = v.z;
            As[ac + 3][ar] = v.w;
        }
        // load B tile (K,N divisible by BK,BN in all our uses)
#pragma unroll
        for (int base = 0; base < BK * BN / 4; base += NT) {
            int idx = base + tid;
            int br = idx / (BN / 4);
            int bc = (idx % (BN / 4)) * 4;
            *(float4*)&Bs[br][bc] = *(const float4*)&B[(size_t)(k0 + br) * Nn + n0 + bc];
        }
        __syncthreads();

#pragma unroll
        for (int kk = 0; kk < BK; kk++) {
            float av[TM];
#pragma unroll
            for (int q = 0; q < TM / 4; q++) {
                float4 a4 = *(const float4*)&As[kk][ty * TM + 4 * q];
                av[4 * q + 0] = a4.x; av[4 * q + 1] = a4.y;
                av[4 * q + 2] = a4.z; av[4 * q + 3] = a4.w;
            }
            float4 b4 = *(const float4*)&Bs[kk][tx * TN];
            unsigned long long bp0 = pack2(b4.x, b4.y);
            unsigned long long bp1 = pack2(b4.z, b4.w);
#pragma unroll
            for (int i = 0; i < TM; i++) {
                unsigned long long ap = pack2(av[i], av[i]);
                asm("fma.rn.f32x2 %0, %1, %2, %0;" : "+l"(acc[i][0]) : "l"(ap), "l"(bp0));
                asm("fma.rn.f32x2 %0, %1, %2, %0;" : "+l"(acc[i][1]) : "l"(ap), "l"(bp1));
            }
        }
        __syncthreads();
    }

    float4 s4, d4;
    if (ATTOUT) {
        s4 = ((const float4*)att_s)[tx];
        d4 = ((const float4*)att_d)[tx];
    }

#pragma unroll
    for (int i = 0; i < TM; i++) {
        int row = m0 + ty * TM + i;
        float2 v01 = unpack2(acc[i][0]);
        float2 v23 = unpack2(acc[i][1]);
        if (row < M) {
            int col = n0 + tx * TN;
            float4 v;
            v.x = v01.x; v.y = v01.y; v.z = v23.x; v.w = v23.y;
            if (OBIAS) {
                v.x += obias[col + 0]; v.y += obias[col + 1];
                v.z += obias[col + 2]; v.w += obias[col + 3];
            }
            *(float4*)&C[(size_t)row * Nn + col] = v;
        }
        if (ATTOUT) {
            // lane == tx (BN/TN == 32); head = tx>>3, 8 lanes per head
            float ps = v01.x * s4.x + v01.y * s4.y + v23.x * s4.z + v23.y * s4.w;
            float pd = v01.x * d4.x + v01.y * d4.y + v23.x * d4.z + v23.y * d4.w;
#pragma unroll
            for (int off = 1; off < 8; off <<= 1) {
                ps += __shfl_xor_sync(0xffffffffu, ps, off);
                pd += __shfl_xor_sync(0xffffffffu, pd, off);
            }
            if ((tx & 7) == 0 && row < M) {
                g_asrc[row * 4 + (tx >> 3)] = ps;
                g_adst[row * 4 + (tx >> 3)] = pd;
            }
        }
    }
}

// ---------------- CSR-by-dst build ------------------------------------------
__global__ void init_deg_kernel() {
    int i = blockIdx.x * blockDim.x + threadIdx.x;
    if (i < NN) g_deg[i] = 0;
}

__global__ void deg_kernel(const void* __restrict__ ei) {
    int e = blockIdx.x * blockDim.x + threadIdx.x;
    if (e < EE) {
        int d = edge_at(ei, EE + e);
        atomicAdd(&g_deg[d], 1);
    }
}

// single-block exclusive scan over g_deg -> g_off / g_cur; g_off[NN] = total.
// warp-shuffle scan: 4 barriers per 1024-chunk instead of 20.
__global__ void __launch_bounds__(1024) scan_kernel() {
    __shared__ int wsum[32];
    __shared__ int s_run;
    int t = threadIdx.x, lane = t & 31, wid = t >> 5;
    if (t == 0) s_run = 0;
    __syncthreads();
    for (int base = 0; base < NN; base += 1024) {
        int idx = base + t;
        int v = (idx < NN) ? g_deg[idx] : 0;
        int x = v;
#pragma unroll
        for (int off = 1; off < 32; off <<= 1) {
            int y = __shfl_up_sync(0xffffffffu, x, off);
            if (lane >= off) x += y;
        }
        if (lane == 31) wsum[wid] = x;
        __syncthreads();
        if (wid == 0) {
            int w = wsum[lane];
#pragma unroll
            for (int off = 1; off < 32; off <<= 1) {
                int y = __shfl_up_sync(0xffffffffu, w, off);
                if (lane >= off) w += y;
            }
            wsum[lane] = w;
        }
        __syncthreads();
        int run = s_run;
        int woff = wid ? wsum[wid - 1] : 0;
        if (idx < NN) {
            int o = run + woff + x - v;
            g_off[idx] = o;
            g_cur[idx] = o;
        }
        __syncthreads();
        if (t == 0) s_run = run + wsum[31];
        __syncthreads();
    }
    if (t == 0) g_off[NN] = s_run;
}

__global__ void scatter_kernel(const void* __restrict__ ei) {
    int e = blockIdx.x * blockDim.x + threadIdx.x;
    if (e < EE) {
        int s = edge_at(ei, e);
        int d = edge_at(ei, EE + e);
        int p = atomicAdd(&g_cur[d], 1);
        g_csr[p] = s;
    }
}

// ---------------- GAT softmax + aggregation ---------------------------------
// One warp per destination node. Lane l: channels 4l..4l+3, head hl = l>>3.
// exp(max) subtraction cancels exactly in alpha = ex/denom, so it is skipped;
// logits are O(1) so __expf never overflows. Self loop folded in directly.
// Edges processed 4 at a time so the csr->asrc/h dependent-load chain runs at
// MLP=4 instead of 1.
__global__ void __launch_bounds__(256) gat_agg_kernel() {
    int i = (blockIdx.x * blockDim.x + threadIdx.x) >> 5;
    int lane = threadIdx.x & 31;
    if (i >= NN) return;
    int hl = lane >> 3;

    const float4* __restrict__ h4 = (const float4*)g_h;

    float ad = g_adst[i * 4 + hl];

    // self loop
    float as = g_asrc[i * 4 + hl];
    float e = as + ad;
    e = e > 0.f ? e : NEG_SLOPE * e;
    float ex = __expf(e);
    float denom = ex;
    float4 hv = h4[(size_t)i * 32 + lane];
    float4 acc;
    acc.x = ex * hv.x; acc.y = ex * hv.y; acc.z = ex * hv.z; acc.w = ex * hv.w;

    int s = g_off[i], t = g_off[i + 1];
    int k = s;
    for (; k + 4 <= t; k += 4) {
        int j0 = g_csr[k + 0], j1 = g_csr[k + 1];
        int j2 = g_csr[k + 2], j3 = g_csr[k + 3];
        float a0 = __ldg(&g_asrc[j0 * 4 + hl]);
        float a1 = __ldg(&g_asrc[j1 * 4 + hl]);
        float a2 = __ldg(&g_asrc[j2 * 4 + hl]);
        float a3 = __ldg(&g_asrc[j3 * 4 + hl]);
        float4 h0 = h4[(size_t)j0 * 32 + lane];
        float4 h1 = h4[(size_t)j1 * 32 + lane];
        float4 h2 = h4[(size_t)j2 * 32 + lane];
        float4 h3 = h4[(size_t)j3 * 32 + lane];
        float e0 = a0 + ad; e0 = e0 > 0.f ? e0 : NEG_SLOPE * e0;
        float e1 = a1 + ad; e1 = e1 > 0.f ? e1 : NEG_SLOPE * e1;
        float e2 = a2 + ad; e2 = e2 > 0.f ? e2 : NEG_SLOPE * e2;
        float e3 = a3 + ad; e3 = e3 > 0.f ? e3 : NEG_SLOPE * e3;
        float x0 = __expf(e0), x1 = __expf(e1), x2 = __expf(e2), x3 = __expf(e3);
        denom += (x0 + x1) + (x2 + x3);
        acc.x += x0 * h0.x + x1 * h1.x + x2 * h2.x + x3 * h3.x;
        acc.y += x0 * h0.y + x1 * h1.y + x2 * h2.y + x3 * h3.y;
        acc.z += x0 * h0.z + x1 * h1.z + x2 * h2.z + x3 * h3.z;
        acc.w += x0 * h0.w + x1 * h1.w + x2 * h2.w + x3 * h3.w;
    }
    for (; k < t; k++) {
        int j = g_csr[k];
        float aj = __ldg(&g_asrc[j * 4 + hl]);
        float4 hj = h4[(size_t)j * 32 + lane];
        float ej = aj + ad;
        ej = ej > 0.f ? ej : NEG_SLOPE * ej;
        float xj = __expf(ej);
        denom += xj;
        acc.x += xj * hj.x; acc.y += xj * hj.y;
        acc.z += xj * hj.z; acc.w += xj * hj.w;
    }
    float inv = 1.f / denom;
    float4 o;
    o.x = acc.x * inv; o.y = acc.y * inv; o.z = acc.z * inv; o.w = acc.w * inv;
    ((float4*)g_agg)[(size_t)i * 32 + lane] = o;
}

// ---------------- launch ----------------------------------------------------
extern "C" void kernel_launch(void* const* d_in, const int* in_sizes, int n_in,
                              void* d_out, int out_size)
{
    const float* x      = (const float*)d_in[0];
    const void*  ei     = d_in[1];           // int32 or int64 — detected on device
    const float* W      = (const float*)d_in[2];
    const float* att_s  = (const float*)d_in[3];
    const float* att_d  = (const float*)d_in[4];
    const float* bias   = (const float*)d_in[5];
    const float* linW   = (const float*)d_in[6];
    const float* linb   = (const float*)d_in[7];
    float* out = (float*)d_out;

    detect_kernel<<<1, 1>>>((const int*)ei);
    init_deg_kernel<<<(NN + 255) / 256, 256>>>();

    // h = x @ W   [50000,256]x[256,128]; fused a_src/a_dst epilogue
    gemm_kernel<64, 128, 16, 8, 4, false, false, false, true, true>
        <<<dim3((NN + 63) / 64, 1), 256>>>(x, W, nullptr, nullptr,
                                           att_s, att_d, nullptr, NN, HC, INC);

    deg_kernel<<<(EE + 255) / 256, 256>>>(ei);
    scan_kernel<<<1, 1024>>>();
    scatter_kernel<<<(EE + 255) / 256, 256>>>(ei);

    gat_agg_kernel<<<(NN + 7) / 8, 256>>>();

    // out = elu(agg + bias) @ lin_W + lin_b   [50000,128]x[128,64]  (A <- g_agg)
    gemm_kernel<128, 64, 16, 8, 4, true, true, true, false, false>
        <<<dim3((NN + 127) / 128, 1), 256>>>(nullptr, linW, bias, linb,
                                             nullptr, nullptr, out, NN, OUTC, HC);
}